// round 9
// baseline (speedup 1.0000x reference)
#include <cuda_runtime.h>
#include <cuda_bf16.h>
#include <cstdint>

#define NF       32
#define NPOLY    6545
#define BATCH    8192
#define MTILE    128
#define NCHUNK   410          // ceil(6545/16) k16-chunks, zero-padded to 6560
#define NSPLIT   8
#define THREADS  256

__device__ uint32_t           g_idx[NPOLY];
__device__ uint4              g_idxfrag[NCHUNK * 4];           // [chunk][q] -> idx of k=2q,2q+1,2q+8,2q+9
__device__ unsigned long long g_wfrag[NCHUNK * 2 * 4 * 32];    // [chunk][plane][ntile][lane] -> {reg0,reg1}
__device__ float              g_part[NSPLIT][BATCH * NF];

// ---------------------------------------------------------------------------
// Monomial index decode: p=0 -> 1 ; [1,33): x_m ; [33,561): x_f*x_m ;
// [561,6545): x_f*(x_g*x_m), m<=g<=f triangular — reference order.
// ---------------------------------------------------------------------------
__device__ uint32_t decode_idx(int p) {
    int a = 32, b = 32, c = 32;
    if (p <= 0 || p >= NPOLY) {
    } else if (p < 33) {
        a = p - 1;
    } else if (p < 561) {
        int q = p - 33;
        int f = (int)((sqrtf(8.0f * (float)q + 1.0f) - 1.0f) * 0.5f);
        if (f < 0) f = 0; if (f > 31) f = 31;
        while (f < 31 && (f + 1) * (f + 2) / 2 <= q) f++;
        while (f > 0 && f * (f + 1) / 2 > q) f--;
        a = f; b = q - f * (f + 1) / 2;
    } else {
        int q = p - 561;
        int f = (int)cbrtf(6.0f * (float)q);
        if (f < 0) f = 0; if (f > 31) f = 31;
        while (f < 31 && (f + 1) * (f + 2) * (f + 3) / 6 <= q) f++;
        while (f > 0 && f * (f + 1) * (f + 2) / 6 > q) f--;
        int r = q - f * (f + 1) * (f + 2) / 6;
        int g = (int)((sqrtf(8.0f * (float)r + 1.0f) - 1.0f) * 0.5f);
        if (g < 0) g = 0; if (g > f) g = f;
        while (g < f && (g + 1) * (g + 2) / 2 <= r) g++;
        while (g > 0 && g * (g + 1) / 2 > r) g--;
        a = f; b = g; c = r - g * (g + 1) / 2;
    }
    return (uint32_t)a | ((uint32_t)b << 8) | ((uint32_t)c << 16);
}

__global__ void build_idx_kernel() {
    int p = blockIdx.x * blockDim.x + threadIdx.x;
    if (p < NPOLY) g_idx[p] = decode_idx(p);
}

__global__ void build_idxfrag_kernel() {
    int e = blockIdx.x * blockDim.x + threadIdx.x;
    if (e >= NCHUNK * 4) return;
    int c = e >> 2, q = e & 3;
    int k0 = c * 16 + 2 * q;
    uint4 v;
    v.x = (k0     < NPOLY) ? g_idx[k0]     : 0x202020u;
    v.y = (k0 + 1 < NPOLY) ? g_idx[k0 + 1] : 0x202020u;
    v.z = (k0 + 8 < NPOLY) ? g_idx[k0 + 8] : 0x202020u;
    v.w = (k0 + 9 < NPOLY) ? g_idx[k0 + 9] : 0x202020u;
    g_idxfrag[e] = v;
}

// W fragments for mma.m16n8k16.row.col B (col-major KxN), hi/lo bf16 planes.
__global__ void build_wfrag_kernel(const float* __restrict__ W) {
    int e = blockIdx.x * blockDim.x + threadIdx.x;
    if (e >= NCHUNK * 2 * 4 * 32) return;
    int lane = e & 31;
    int nt   = (e >> 5) & 3;
    int p    = (e >> 7) & 1;
    int c    = e >> 8;
    int q    = lane & 3;
    int n    = nt * 8 + (lane >> 2);

    unsigned long long out = 0;
#pragma unroll
    for (int half = 0; half < 2; ++half) {
        uint32_t reg = 0;
#pragma unroll
        for (int j = 0; j < 2; ++j) {
            int k = c * 16 + 2 * q + half * 8 + j;
            float w = (k < NPOLY) ? W[k * NF + n] : 0.0f;
            __nv_bfloat16 h = __float2bfloat16(w);
            __nv_bfloat16 val = (p == 0) ? h : __float2bfloat16(w - __bfloat162float(h));
            reg |= (uint32_t)__bfloat16_as_ushort(val) << (16 * j);
        }
        out |= (unsigned long long)reg << (32 * half);
    }
    g_wfrag[e] = out;
}

// ---------------------------------------------------------------------------
__device__ __forceinline__ void mma16816(float* d, const uint32_t* a,
                                         uint32_t b0, uint32_t b1) {
    asm("mma.sync.aligned.m16n8k16.row.col.f32.bf16.bf16.f32 "
        "{%0,%1,%2,%3}, {%4,%5,%6,%7}, {%8,%9}, {%0,%1,%2,%3};"
        : "+f"(d[0]), "+f"(d[1]), "+f"(d[2]), "+f"(d[3])
        : "r"(a[0]), "r"(a[1]), "r"(a[2]), "r"(a[3]), "r"(b0), "r"(b1));
}

__device__ __forceinline__ uint32_t packbf2(float lo, float hi) {
    __nv_bfloat162 t = __floats2bfloat162_rn(lo, hi);   // .x = lo half
    return *(uint32_t*)&t;
}

// ---------------------------------------------------------------------------
// Main fused kernel: CTA = 128-row M-tile x one K-eighth. 8 warps, each a
// 16-row stripe x full N=32. x tile stored row-PAIRED (float2 = rows r, r+8)
// so each monomial needs 3 LDS.64 instead of 6 LDS.32. Register-double-
// buffered global loads; no __syncthreads in the main loop.
// ---------------------------------------------------------------------------
__global__ __launch_bounds__(THREADS, 3)
void taylor_mma_kernel(const float* __restrict__ x) {
    // [feature][pair]; pair p = warp*8+gid -> rows {16*warp+gid, 16*warp+gid+8}
    // stride 65 float2 = 130 words = 2 mod 32: same-pair q-lanes conflict only
    // for feat == feat' (mod 16).
    __shared__ float2 xt2[33][65];

    const int tid   = threadIdx.x;
    const int lane  = tid & 31;
    const int warp  = tid >> 5;
    const int gid   = lane >> 2;
    const int q     = lane & 3;
    const int tile  = blockIdx.x >> 3;
    const int split = blockIdx.x & 7;
    const int row0  = tile * MTILE;
    const int r0    = warp * 16 + gid;
    const int r1    = r0 + 8;
    const int pair  = warp * 8 + gid;

    for (int e = tid; e < MTILE * NF; e += THREADS) {
        int rr = e >> 5, ii = e & 31;
        int pp = (rr >> 4) * 8 + (rr & 7);
        int comp = (rr >> 3) & 1;
        (&xt2[ii][pp].x)[comp] = x[(row0 + rr) * NF + ii];
    }
    if (tid < 64) xt2[32][tid] = make_float2(1.0f, 1.0f);
    __syncthreads();

    float acc[4][4];
#pragma unroll
    for (int nt = 0; nt < 4; ++nt)
#pragma unroll
        for (int j = 0; j < 4; ++j) acc[nt][j] = 0.0f;

    // split s: 410 = 8*51 + 2 -> first two splits take 52
    const int cbase = 51 * split + (split < 2 ? split : 2);
    const int nch   = 51 + (split < 2 ? 1 : 0);
    const float2* xp = &xt2[0][pair];

    // ---- prologue: load chunk cbase ----
    uint4 id_cur = g_idxfrag[cbase * 4 + q];
    unsigned long long Bh_cur[4], Bl_cur[4];
    {
        const unsigned long long* wp = &g_wfrag[(size_t)cbase * 256 + lane];
#pragma unroll
        for (int nt = 0; nt < 4; ++nt) {
            Bh_cur[nt] = wp[nt * 32];
            Bl_cur[nt] = wp[128 + nt * 32];
        }
    }

#pragma unroll 2
    for (int i = 0; i < nch; ++i) {
        // ---- prefetch chunk i+1 ----
        uint4 id_nxt;
        unsigned long long Bh_nxt[4], Bl_nxt[4];
        if (i + 1 < nch) {
            const int cn = cbase + i + 1;
            id_nxt = g_idxfrag[cn * 4 + q];
            const unsigned long long* wp = &g_wfrag[(size_t)cn * 256 + lane];
#pragma unroll
            for (int nt = 0; nt < 4; ++nt) {
                Bh_nxt[nt] = wp[nt * 32];
                Bl_nxt[nt] = wp[128 + nt * 32];
            }
        }

        // ---- evaluate 4 monomials x 2 rows (row-paired LDS.64) ----
        float2 v[4];
        {
            const uint32_t ids[4] = {id_cur.x, id_cur.y, id_cur.z, id_cur.w};
#pragma unroll
            for (int j = 0; j < 4; ++j) {
                const uint32_t id = ids[j];
                const float2 fa = xp[(id & 255) * 65];
                const float2 fb = xp[((id >> 8) & 255) * 65];
                const float2 fc = xp[((id >> 16) & 255) * 65];
                v[j].x = fa.x * (fb.x * fc.x);
                v[j].y = fa.y * (fb.y * fc.y);
            }
        }

        // ---- A fragments: hi plane + residual lo plane ----
        // Ah[0]=(r0: k,k+1) Ah[1]=(r1: k,k+1) Ah[2]=(r0: k8,k9) Ah[3]=(r1: k8,k9)
        uint32_t Ah[4], Al[4];
        Ah[0] = packbf2(v[0].x, v[1].x);
        Ah[1] = packbf2(v[0].y, v[1].y);
        Ah[2] = packbf2(v[2].x, v[3].x);
        Ah[3] = packbf2(v[2].y, v[3].y);
#pragma unroll
        for (int hh = 0; hh < 2; ++hh) {
            {
                uint32_t u = Ah[hh * 2];
                float f0 = __uint_as_float(u << 16);
                float f1 = __uint_as_float(u & 0xffff0000u);
                Al[hh * 2] = packbf2(v[hh * 2].x - f0, v[hh * 2 + 1].x - f1);
            }
            {
                uint32_t u = Ah[hh * 2 + 1];
                float f0 = __uint_as_float(u << 16);
                float f1 = __uint_as_float(u & 0xffff0000u);
                Al[hh * 2 + 1] = packbf2(v[hh * 2].y - f0, v[hh * 2 + 1].y - f1);
            }
        }

        // ---- 4 n-tiles x 3 plane terms ----
#pragma unroll
        for (int nt = 0; nt < 4; ++nt) {
            uint32_t bh0 = (uint32_t)Bh_cur[nt], bh1 = (uint32_t)(Bh_cur[nt] >> 32);
            uint32_t bl0 = (uint32_t)Bl_cur[nt], bl1 = (uint32_t)(Bl_cur[nt] >> 32);
            mma16816(acc[nt], Ah, bh0, bh1);
            mma16816(acc[nt], Ah, bl0, bl1);
            mma16816(acc[nt], Al, bh0, bh1);
        }

        // ---- rotate double buffer ----
        if (i + 1 < nch) {
            id_cur = id_nxt;
#pragma unroll
            for (int nt = 0; nt < 4; ++nt) {
                Bh_cur[nt] = Bh_nxt[nt];
                Bl_cur[nt] = Bl_nxt[nt];
            }
        }
    }

    // ---- epilogue: write partial ----
    float* dst = g_part[split];
#pragma unroll
    for (int nt = 0; nt < 4; ++nt) {
        int col = nt * 8 + 2 * q;
        *(float2*)&dst[(row0 + r0) * NF + col] = make_float2(acc[nt][0], acc[nt][1]);
        *(float2*)&dst[(row0 + r1) * NF + col] = make_float2(acc[nt][2], acc[nt][3]);
    }
}

__global__ void reduce_kernel(const float* __restrict__ x, float* __restrict__ out) {
    int i = blockIdx.x * blockDim.x + threadIdx.x;
    if (i >= BATCH * NF / 4) return;
    float4 o = ((const float4*)x)[i];
#pragma unroll
    for (int s = 0; s < NSPLIT; ++s) {
        float4 p = ((const float4*)g_part[s])[i];
        o.x += p.x; o.y += p.y; o.z += p.z; o.w += p.w;
    }
    ((float4*)out)[i] = o;
}

extern "C" void kernel_launch(void* const* d_in, const int* in_sizes, int n_in,
                              void* d_out, int out_size) {
    const float* x = (const float*)d_in[0];
    const float* W = (const float*)d_in[1];
    if (n_in >= 2 && in_sizes[0] == NPOLY * NF && in_sizes[1] == BATCH * NF) {
        x = (const float*)d_in[1];
        W = (const float*)d_in[0];
    }
    float* out = (float*)d_out;

    build_idx_kernel<<<(NPOLY + 255) / 256, 256>>>();
    build_idxfrag_kernel<<<(NCHUNK * 4 + 255) / 256, 256>>>();
    build_wfrag_kernel<<<(NCHUNK * 2 * 4 * 32 + 255) / 256, 256>>>(W);
    taylor_mma_kernel<<<(BATCH / MTILE) * NSPLIT, THREADS>>>(x);
    reduce_kernel<<<(BATCH * NF / 4 + 255) / 256, 256>>>(x, out);
}

// round 10
// speedup vs baseline: 1.1108x; 1.1108x over previous
#include <cuda_runtime.h>
#include <cuda_bf16.h>
#include <cstdint>

#define NF       32
#define NPOLY    6545
#define BATCH    8192
#define MTILE    64
#define NCHUNK   410          // ceil(6545/16) k16-chunks, zero-padded to 6560
#define NSPLIT   8
#define THREADS  128

__device__ uint32_t           g_idx[NPOLY];
__device__ uint4              g_idxfrag[NCHUNK * 4];           // [chunk][q] -> idx of k=2q,2q+1,2q+8,2q+9
__device__ unsigned long long g_wfrag[NCHUNK * 2 * 4 * 32];    // [chunk][plane][ntile][lane] -> {reg0,reg1}
__device__ float              g_part[NSPLIT][BATCH * NF];

// ---------------------------------------------------------------------------
// Monomial index decode: p=0 -> 1 ; [1,33): x_m ; [33,561): x_f*x_m ;
// [561,6545): x_f*(x_g*x_m), m<=g<=f triangular — reference order.
// ---------------------------------------------------------------------------
__device__ uint32_t decode_idx(int p) {
    int a = 32, b = 32, c = 32;
    if (p <= 0 || p >= NPOLY) {
    } else if (p < 33) {
        a = p - 1;
    } else if (p < 561) {
        int q = p - 33;
        int f = (int)((sqrtf(8.0f * (float)q + 1.0f) - 1.0f) * 0.5f);
        if (f < 0) f = 0; if (f > 31) f = 31;
        while (f < 31 && (f + 1) * (f + 2) / 2 <= q) f++;
        while (f > 0 && f * (f + 1) / 2 > q) f--;
        a = f; b = q - f * (f + 1) / 2;
    } else {
        int q = p - 561;
        int f = (int)cbrtf(6.0f * (float)q);
        if (f < 0) f = 0; if (f > 31) f = 31;
        while (f < 31 && (f + 1) * (f + 2) * (f + 3) / 6 <= q) f++;
        while (f > 0 && f * (f + 1) * (f + 2) / 6 > q) f--;
        int r = q - f * (f + 1) * (f + 2) / 6;
        int g = (int)((sqrtf(8.0f * (float)r + 1.0f) - 1.0f) * 0.5f);
        if (g < 0) g = 0; if (g > f) g = f;
        while (g < f && (g + 1) * (g + 2) / 2 <= r) g++;
        while (g > 0 && g * (g + 1) / 2 > r) g--;
        a = f; b = g; c = r - g * (g + 1) / 2;
    }
    return (uint32_t)a | ((uint32_t)b << 8) | ((uint32_t)c << 16);
}

__global__ void build_idx_kernel() {
    int p = blockIdx.x * blockDim.x + threadIdx.x;
    if (p < NPOLY) g_idx[p] = decode_idx(p);
}

__global__ void build_idxfrag_kernel() {
    int e = blockIdx.x * blockDim.x + threadIdx.x;
    if (e >= NCHUNK * 4) return;
    int c = e >> 2, q = e & 3;
    int k0 = c * 16 + 2 * q;
    uint4 v;
    v.x = (k0     < NPOLY) ? g_idx[k0]     : 0x202020u;
    v.y = (k0 + 1 < NPOLY) ? g_idx[k0 + 1] : 0x202020u;
    v.z = (k0 + 8 < NPOLY) ? g_idx[k0 + 8] : 0x202020u;
    v.w = (k0 + 9 < NPOLY) ? g_idx[k0 + 9] : 0x202020u;
    g_idxfrag[e] = v;
}

// W fragments for mma.m16n8k16.row.col B (col-major KxN), hi/lo bf16 planes.
__global__ void build_wfrag_kernel(const float* __restrict__ W) {
    int e = blockIdx.x * blockDim.x + threadIdx.x;
    if (e >= NCHUNK * 2 * 4 * 32) return;
    int lane = e & 31;
    int nt   = (e >> 5) & 3;
    int p    = (e >> 7) & 1;
    int c    = e >> 8;
    int q    = lane & 3;
    int n    = nt * 8 + (lane >> 2);

    unsigned long long out = 0;
#pragma unroll
    for (int half = 0; half < 2; ++half) {
        uint32_t reg = 0;
#pragma unroll
        for (int j = 0; j < 2; ++j) {
            int k = c * 16 + 2 * q + half * 8 + j;
            float w = (k < NPOLY) ? W[k * NF + n] : 0.0f;
            __nv_bfloat16 h = __float2bfloat16(w);
            __nv_bfloat16 val = (p == 0) ? h : __float2bfloat16(w - __bfloat162float(h));
            reg |= (uint32_t)__bfloat16_as_ushort(val) << (16 * j);
        }
        out |= (unsigned long long)reg << (32 * half);
    }
    g_wfrag[e] = out;
}

// ---------------------------------------------------------------------------
__device__ __forceinline__ void mma16816(float* d, const uint32_t* a,
                                         uint32_t b0, uint32_t b1) {
    asm("mma.sync.aligned.m16n8k16.row.col.f32.bf16.bf16.f32 "
        "{%0,%1,%2,%3}, {%4,%5,%6,%7}, {%8,%9}, {%0,%1,%2,%3};"
        : "+f"(d[0]), "+f"(d[1]), "+f"(d[2]), "+f"(d[3])
        : "r"(a[0]), "r"(a[1]), "r"(a[2]), "r"(a[3]), "r"(b0), "r"(b1));
}

__device__ __forceinline__ uint32_t packbf2(float lo, float hi) {
    __nv_bfloat162 t = __floats2bfloat162_rn(lo, hi);   // .x = lo half
    return *(uint32_t*)&t;
}

// ---------------------------------------------------------------------------
// Main fused kernel: CTA = 64-row M-tile x one K-eighth. 4 warps, each a
// 16-row stripe x full N=32. Small CTAs -> 6 resident/SM (24 warps).
// Register-double-buffered global loads; no __syncthreads in the main loop.
// ---------------------------------------------------------------------------
__global__ __launch_bounds__(THREADS, 6)
void taylor_mma_kernel(const float* __restrict__ x) {
    // row stride 65 (odd): bank = feat + row (mod 32); per-q 8 consecutive
    // rows -> conflict-free; cross-q degree <= 4.
    __shared__ float xt[33][65];

    const int tid   = threadIdx.x;
    const int lane  = tid & 31;
    const int warp  = tid >> 5;          // 0..3
    const int gid   = lane >> 2;         // 0..7
    const int q     = lane & 3;          // 0..3
    const int tile  = blockIdx.x >> 3;
    const int split = blockIdx.x & 7;
    const int row0  = tile * MTILE;
    const int r0    = warp * 16 + gid;   // local rows r0, r0+8 (0..63)
    const int r1    = r0 + 8;

    for (int e = tid; e < MTILE * NF; e += THREADS) {
        int rr = e >> 5, ii = e & 31;
        xt[ii][rr] = x[(row0 + rr) * NF + ii];
    }
    if (tid < MTILE) xt[32][tid] = 1.0f;
    __syncthreads();

    float acc[4][4];
#pragma unroll
    for (int nt = 0; nt < 4; ++nt)
#pragma unroll
        for (int j = 0; j < 4; ++j) acc[nt][j] = 0.0f;

    // split s: 410 = 8*51 + 2 -> first two splits take 52
    const int cbase = 51 * split + (split < 2 ? split : 2);
    const int nch   = 51 + (split < 2 ? 1 : 0);
    const float* xr0 = &xt[0][r0];
    const float* xr1 = &xt[0][r1];

    // ---- prologue: load chunk cbase ----
    uint4 id_cur = g_idxfrag[cbase * 4 + q];
    unsigned long long Bh_cur[4], Bl_cur[4];
    {
        const unsigned long long* wp = &g_wfrag[(size_t)cbase * 256 + lane];
#pragma unroll
        for (int nt = 0; nt < 4; ++nt) {
            Bh_cur[nt] = wp[nt * 32];
            Bl_cur[nt] = wp[128 + nt * 32];
        }
    }

#pragma unroll 2
    for (int i = 0; i < nch; ++i) {
        // ---- prefetch chunk i+1 (latency overlapped with compute below) ----
        uint4 id_nxt;
        unsigned long long Bh_nxt[4], Bl_nxt[4];
        if (i + 1 < nch) {
            const int cn = cbase + i + 1;
            id_nxt = g_idxfrag[cn * 4 + q];
            const unsigned long long* wp = &g_wfrag[(size_t)cn * 256 + lane];
#pragma unroll
            for (int nt = 0; nt < 4; ++nt) {
                Bh_nxt[nt] = wp[nt * 32];
                Bl_nxt[nt] = wp[128 + nt * 32];
            }
        }

        // ---- evaluate 8 monomials (this thread's A fragment) ----
        float v0[4], v1[4];
        {
            const uint32_t ids[4] = {id_cur.x, id_cur.y, id_cur.z, id_cur.w};
#pragma unroll
            for (int j = 0; j < 4; ++j) {
                const uint32_t id = ids[j];
                const int a  = id & 255;
                const int b  = (id >> 8) & 255;
                const int cc = (id >> 16) & 255;
                v0[j] = xr0[a * 65] * (xr0[b * 65] * xr0[cc * 65]);
                v1[j] = xr1[a * 65] * (xr1[b * 65] * xr1[cc * 65]);
            }
        }

        // ---- A fragments: hi plane + residual lo plane ----
        uint32_t Ah[4], Al[4];
        Ah[0] = packbf2(v0[0], v0[1]);
        Ah[1] = packbf2(v1[0], v1[1]);
        Ah[2] = packbf2(v0[2], v0[3]);
        Ah[3] = packbf2(v1[2], v1[3]);
#pragma unroll
        for (int hh = 0; hh < 2; ++hh) {
            {
                uint32_t u = Ah[hh * 2];
                float f0 = __uint_as_float(u << 16);
                float f1 = __uint_as_float(u & 0xffff0000u);
                Al[hh * 2] = packbf2(v0[hh * 2] - f0, v0[hh * 2 + 1] - f1);
            }
            {
                uint32_t u = Ah[hh * 2 + 1];
                float f0 = __uint_as_float(u << 16);
                float f1 = __uint_as_float(u & 0xffff0000u);
                Al[hh * 2 + 1] = packbf2(v1[hh * 2] - f0, v1[hh * 2 + 1] - f1);
            }
        }

        // ---- 4 n-tiles x 3 plane terms ----
#pragma unroll
        for (int nt = 0; nt < 4; ++nt) {
            uint32_t bh0 = (uint32_t)Bh_cur[nt], bh1 = (uint32_t)(Bh_cur[nt] >> 32);
            uint32_t bl0 = (uint32_t)Bl_cur[nt], bl1 = (uint32_t)(Bl_cur[nt] >> 32);
            mma16816(acc[nt], Ah, bh0, bh1);
            mma16816(acc[nt], Ah, bl0, bl1);
            mma16816(acc[nt], Al, bh0, bh1);
        }

        // ---- rotate double buffer ----
        if (i + 1 < nch) {
            id_cur = id_nxt;
#pragma unroll
            for (int nt = 0; nt < 4; ++nt) {
                Bh_cur[nt] = Bh_nxt[nt];
                Bl_cur[nt] = Bl_nxt[nt];
            }
        }
    }

    // ---- epilogue: write partial ----
    float* dst = g_part[split];
#pragma unroll
    for (int nt = 0; nt < 4; ++nt) {
        int col = nt * 8 + 2 * q;
        *(float2*)&dst[(row0 + r0) * NF + col] = make_float2(acc[nt][0], acc[nt][1]);
        *(float2*)&dst[(row0 + r1) * NF + col] = make_float2(acc[nt][2], acc[nt][3]);
    }
}

__global__ void reduce_kernel(const float* __restrict__ x, float* __restrict__ out) {
    int i = blockIdx.x * blockDim.x + threadIdx.x;
    if (i >= BATCH * NF / 4) return;
    float4 o = ((const float4*)x)[i];
#pragma unroll
    for (int s = 0; s < NSPLIT; ++s) {
        float4 p = ((const float4*)g_part[s])[i];
        o.x += p.x; o.y += p.y; o.z += p.z; o.w += p.w;
    }
    ((float4*)out)[i] = o;
}

extern "C" void kernel_launch(void* const* d_in, const int* in_sizes, int n_in,
                              void* d_out, int out_size) {
    const float* x = (const float*)d_in[0];
    const float* W = (const float*)d_in[1];
    if (n_in >= 2 && in_sizes[0] == NPOLY * NF && in_sizes[1] == BATCH * NF) {
        x = (const float*)d_in[1];
        W = (const float*)d_in[0];
    }
    float* out = (float*)d_out;

    build_idx_kernel<<<(NPOLY + 255) / 256, 256>>>();
    build_idxfrag_kernel<<<(NCHUNK * 4 + 255) / 256, 256>>>();
    build_wfrag_kernel<<<(NCHUNK * 2 * 4 * 32 + 255) / 256, 256>>>(W);
    taylor_mma_kernel<<<(BATCH / MTILE) * NSPLIT, THREADS>>>(x);
    reduce_kernel<<<(BATCH * NF / 4 + 255) / 256, 256>>>(x, out);
}

// round 12
// speedup vs baseline: 1.2111x; 1.0903x over previous
#include <cuda_runtime.h>
#include <cuda_bf16.h>
#include <cstdint>

#define NF       32
#define NPOLY    6545
#define BATCH    8192
#define MTILE    64
#define NRUNS    561
#define KPAD     7440          // 465 chunks * 16 (padded logical K; used slots 7428)
#define NCHUNKP  465
#define NSPLIT   6
#define THREADS  128

__device__ int                g_slot2p[KPAD];               // logical slot -> monomial p (-1 = pad)
__device__ unsigned long long g_sched[NCHUNKP * 4];         // [chunk][q]: f|g<<8|m0<<16|m1<<24|m2<<32|m3<<40
__device__ unsigned long long g_wfrag[NCHUNKP * 2 * 4 * 32];// [chunk][plane][ntile][lane] -> {reg0,reg1}
__device__ float              g_part[NSPLIT][BATCH * NF];

// ---------------------------------------------------------------------------
// init: default sched = all-32 (h=1, m=1 -> value 1), slot2p = -1 (W weight 0)
// ---------------------------------------------------------------------------
__global__ void init_sched_kernel() {
    int i = blockIdx.x * blockDim.x + threadIdx.x;
    if (i < KPAD) g_slot2p[i] = -1;
    if (i < NCHUNKP * 4) g_sched[i] = 0x0000202020202020ull;
}

// ---------------------------------------------------------------------------
// One thread per run. Runs (in reference order) have constant h = x_f * x_g:
//   run 0: level<=1, (f,g)=(32,32), L=33, m-list = {32, 0..31}, p = 0..32
//   runs 1..32: level2, f=0..31, g=32, L=f+1, m=0..f, p = 33 + T2(f) + m
//   runs 33..560: level3, (f,g) lex, L=g+1, m=0..g, p = 561 + T3(f) + T2(g) + m
// Each run is padded to a multiple of 4; groups of 4 logical slots map to one
// (chunk, q) sched word and 4 physical k-slots 2q+(e&1)+8*(e>>1).
// ---------------------------------------------------------------------------
__global__ void build_sched_kernel() {
    int r = blockIdx.x * blockDim.x + threadIdx.x;
    if (r >= NRUNS) return;

    int f, g, L, base_p, off;
    if (r == 0) {
        f = 32; g = 32; L = 33; base_p = 0; off = 0;
    } else if (r <= 32) {
        int ff = r - 1;
        f = ff; g = 32; L = ff + 1;
        base_p = 33 + ff * (ff + 1) / 2;
        off = 36;
        for (int t = 0; t < ff; ++t) off += ((t + 4) / 4) * 4;   // ceil((t+1)/4)*4
    } else {
        int rr = r - 33;                       // = f(f+1)/2 + g
        int ff = (int)((sqrtf(8.0f * (float)rr + 1.0f) - 1.0f) * 0.5f);
        if (ff < 0) ff = 0; if (ff > 31) ff = 31;
        while (ff < 31 && (ff + 1) * (ff + 2) / 2 <= rr) ff++;
        while (ff > 0 && ff * (ff + 1) / 2 > rr) ff--;
        int gg = rr - ff * (ff + 1) / 2;
        f = ff; g = gg; L = gg + 1;
        base_p = 561 + ff * (ff + 1) * (ff + 2) / 6 + gg * (gg + 1) / 2;
        off = 612;                             // 36 + 576 (levels <=2 padded)
        for (int t = 0; t < ff; ++t)
            for (int u = 0; u <= t; ++u) off += ((u + 4) / 4) * 4;
        for (int u = 0; u < gg; ++u) off += ((u + 4) / 4) * 4;
    }

    int P = ((L + 3) / 4) * 4;
    for (int i0 = 0; i0 < P; i0 += 4) {
        unsigned long long sc = (unsigned long long)f | ((unsigned long long)g << 8);
#pragma unroll
        for (int e = 0; e < 4; ++e) {
            int i = i0 + e;
            int m, p;
            if (r == 0) {
                if (i == 0)      { m = 32;    p = 0; }
                else if (i < L)  { m = i - 1; p = i; }
                else             { m = 32;    p = -1; }
            } else {
                if (i < L)       { m = i;     p = base_p + i; }
                else             { m = 32;    p = -1; }
            }
            sc |= (unsigned long long)m << (16 + 8 * e);
            g_slot2p[off + i] = p;
        }
        int s = off + i0;
        int c = s >> 4, q = (s >> 2) & 3;
        g_sched[c * 4 + q] = sc;
    }
}

// W fragments for mma.m16n8k16.row.col B (col-major KxN), hi/lo bf16 planes.
// Physical k-slot (2q + j + 8*half) holds the monomial of logical slot
// c*16 + q*4 + (j + 2*half); padding -> 0.
__global__ void build_wfrag_kernel(const float* __restrict__ W) {
    int e = blockIdx.x * blockDim.x + threadIdx.x;
    if (e >= NCHUNKP * 2 * 4 * 32) return;
    int lane = e & 31;
    int nt   = (e >> 5) & 3;
    int pl   = (e >> 7) & 1;
    int c    = e >> 8;
    int q    = lane & 3;
    int n    = nt * 8 + (lane >> 2);

    unsigned long long out = 0;
#pragma unroll
    for (int half = 0; half < 2; ++half) {
        uint32_t reg = 0;
#pragma unroll
        for (int j = 0; j < 2; ++j) {
            int s = c * 16 + q * 4 + j + 2 * half;
            int p = g_slot2p[s];
            float w = (p >= 0) ? W[p * NF + n] : 0.0f;
            __nv_bfloat16 h = __float2bfloat16(w);
            __nv_bfloat16 val = (pl == 0) ? h : __float2bfloat16(w - __bfloat162float(h));
            reg |= (uint32_t)__bfloat16_as_ushort(val) << (16 * j);
        }
        out |= (unsigned long long)reg << (32 * half);
    }
    g_wfrag[e] = out;
}

// ---------------------------------------------------------------------------
__device__ __forceinline__ void mma16816(float* d, const uint32_t* a,
                                         uint32_t b0, uint32_t b1) {
    asm("mma.sync.aligned.m16n8k16.row.col.f32.bf16.bf16.f32 "
        "{%0,%1,%2,%3}, {%4,%5,%6,%7}, {%8,%9}, {%0,%1,%2,%3};"
        : "+f"(d[0]), "+f"(d[1]), "+f"(d[2]), "+f"(d[3])
        : "r"(a[0]), "r"(a[1]), "r"(a[2]), "r"(a[3]), "r"(b0), "r"(b1));
}

__device__ __forceinline__ uint32_t packbf2(float lo, float hi) {
    __nv_bfloat162 t = __floats2bfloat162_rn(lo, hi);   // .x = lo half
    return *(uint32_t*)&t;
}

// ---------------------------------------------------------------------------
// Main fused kernel: CTA = 64-row M-tile x one K-sixth. 4 warps, each a
// 16-row stripe x full N=32. Each thread's 4 k-slots share one h = x_f*x_g:
// eval = 12 LDS + 10 FMUL per chunk (vs 24 LDS + 16 FMUL unscheduled).
// Single-wave grid (768 CTAs, 6/SM). No __syncthreads in the main loop.
// ---------------------------------------------------------------------------
__global__ __launch_bounds__(THREADS, 6)
void taylor_mma_kernel(const float* __restrict__ x) {
    __shared__ float xt[33][65];   // row stride 65: bank = feat + row (mod 32)

    const int tid   = threadIdx.x;
    const int lane  = tid & 31;
    const int warp  = tid >> 5;          // 0..3
    const int gid   = lane >> 2;         // 0..7
    const int q     = lane & 3;          // 0..3
    const int tile  = blockIdx.x / NSPLIT;
    const int split = blockIdx.x % NSPLIT;
    const int row0  = tile * MTILE;
    const int r0    = warp * 16 + gid;
    const int r1    = r0 + 8;

    for (int e = tid; e < MTILE * NF; e += THREADS) {
        int rr = e >> 5, ii = e & 31;
        xt[ii][rr] = x[(row0 + rr) * NF + ii];
    }
    if (tid < MTILE) xt[32][tid] = 1.0f;
    __syncthreads();

    float acc[4][4];
#pragma unroll
    for (int nt = 0; nt < 4; ++nt)
#pragma unroll
        for (int j = 0; j < 4; ++j) acc[nt][j] = 0.0f;

    // 465 = 6*77 + 3 -> splits 0..2 take 78 chunks, 3..5 take 77
    const int cbase = 77 * split + (split < 3 ? split : 3);
    const int nch   = 77 + (split < 3 ? 1 : 0);
    const float* xr0 = &xt[0][r0];
    const float* xr1 = &xt[0][r1];

    // ---- prologue: load chunk cbase ----
    unsigned long long sc_cur = g_sched[cbase * 4 + q];
    unsigned long long Bh_cur[4], Bl_cur[4];
    {
        const unsigned long long* wp = &g_wfrag[(size_t)cbase * 256 + lane];
#pragma unroll
        for (int nt = 0; nt < 4; ++nt) {
            Bh_cur[nt] = wp[nt * 32];
            Bl_cur[nt] = wp[128 + nt * 32];
        }
    }

#pragma unroll 2
    for (int i = 0; i < nch; ++i) {
        // ---- prefetch chunk i+1 (overlaps compute below) ----
        unsigned long long sc_nxt;
        unsigned long long Bh_nxt[4], Bl_nxt[4];
        if (i + 1 < nch) {
            const int cn = cbase + i + 1;
            sc_nxt = g_sched[cn * 4 + q];
            const unsigned long long* wp = &g_wfrag[(size_t)cn * 256 + lane];
#pragma unroll
            for (int nt = 0; nt < 4; ++nt) {
                Bh_nxt[nt] = wp[nt * 32];
                Bl_nxt[nt] = wp[128 + nt * 32];
            }
        }

        // ---- evaluate: one shared h per row, 4 m-multiplies per row ----
        const int f  = (int)(sc_cur & 255);
        const int g  = (int)((sc_cur >> 8) & 255);
        const int m0 = (int)((sc_cur >> 16) & 255);
        const int m1 = (int)((sc_cur >> 24) & 255);
        const int m2 = (int)((sc_cur >> 32) & 255);
        const int m3 = (int)((sc_cur >> 40) & 255);
        const float h0 = xr0[f * 65] * xr0[g * 65];
        const float h1 = xr1[f * 65] * xr1[g * 65];
        float v0[4], v1[4];
        v0[0] = h0 * xr0[m0 * 65];  v1[0] = h1 * xr1[m0 * 65];
        v0[1] = h0 * xr0[m1 * 65];  v1[1] = h1 * xr1[m1 * 65];
        v0[2] = h0 * xr0[m2 * 65];  v1[2] = h1 * xr1[m2 * 65];
        v0[3] = h0 * xr0[m3 * 65];  v1[3] = h1 * xr1[m3 * 65];

        // ---- A fragments: hi plane + residual lo plane ----
        uint32_t Ah[4], Al[4];
        Ah[0] = packbf2(v0[0], v0[1]);
        Ah[1] = packbf2(v1[0], v1[1]);
        Ah[2] = packbf2(v0[2], v0[3]);
        Ah[3] = packbf2(v1[2], v1[3]);
#pragma unroll
        for (int hh = 0; hh < 2; ++hh) {
            {
                uint32_t u = Ah[hh * 2];
                float f0 = __uint_as_float(u << 16);
                float f1 = __uint_as_float(u & 0xffff0000u);
                Al[hh * 2] = packbf2(v0[hh * 2] - f0, v0[hh * 2 + 1] - f1);
            }
            {
                uint32_t u = Ah[hh * 2 + 1];
                float f0 = __uint_as_float(u << 16);
                float f1 = __uint_as_float(u & 0xffff0000u);
                Al[hh * 2 + 1] = packbf2(v1[hh * 2] - f0, v1[hh * 2 + 1] - f1);
            }
        }

        // ---- 4 n-tiles x 3 plane terms ----
#pragma unroll
        for (int nt = 0; nt < 4; ++nt) {
            uint32_t bh0 = (uint32_t)Bh_cur[nt], bh1 = (uint32_t)(Bh_cur[nt] >> 32);
            uint32_t bl0 = (uint32_t)Bl_cur[nt], bl1 = (uint32_t)(Bl_cur[nt] >> 32);
            mma16816(acc[nt], Ah, bh0, bh1);
            mma16816(acc[nt], Ah, bl0, bl1);
            mma16816(acc[nt], Al, bh0, bh1);
        }

        // ---- rotate double buffer ----
        if (i + 1 < nch) {
            sc_cur = sc_nxt;
#pragma unroll
            for (int nt = 0; nt < 4; ++nt) {
                Bh_cur[nt] = Bh_nxt[nt];
                Bl_cur[nt] = Bl_nxt[nt];
            }
        }
    }

    // ---- epilogue: write partial ----
    float* dst = g_part[split];
#pragma unroll
    for (int nt = 0; nt < 4; ++nt) {
        int col = nt * 8 + 2 * q;
        *(float2*)&dst[(row0 + r0) * NF + col] = make_float2(acc[nt][0], acc[nt][1]);
        *(float2*)&dst[(row0 + r1) * NF + col] = make_float2(acc[nt][2], acc[nt][3]);
    }
}

__global__ void reduce_kernel(const float* __restrict__ x, float* __restrict__ out) {
    int i = blockIdx.x * blockDim.x + threadIdx.x;
    if (i >= BATCH * NF / 4) return;
    float4 o = ((const float4*)x)[i];
#pragma unroll
    for (int s = 0; s < NSPLIT; ++s) {
        float4 p = ((const float4*)g_part[s])[i];
        o.x += p.x; o.y += p.y; o.z += p.z; o.w += p.w;
    }
    ((float4*)out)[i] = o;
}

extern "C" void kernel_launch(void* const* d_in, const int* in_sizes, int n_in,
                              void* d_out, int out_size) {
    const float* x = (const float*)d_in[0];
    const float* W = (const float*)d_in[1];
    if (n_in >= 2 && in_sizes[0] == NPOLY * NF && in_sizes[1] == BATCH * NF) {
        x = (const float*)d_in[1];
        W = (const float*)d_in[0];
    }
    float* out = (float*)d_out;

    init_sched_kernel<<<(KPAD + 255) / 256, 256>>>();
    build_sched_kernel<<<(NRUNS + 127) / 128, 128>>>();
    build_wfrag_kernel<<<(NCHUNKP * 2 * 4 * 32 + 255) / 256, 256>>>(W);
    taylor_mma_kernel<<<(BATCH / MTILE) * NSPLIT, THREADS>>>(x);
    reduce_kernel<<<(BATCH * NF / 4 + 255) / 256, 256>>>(x, out);
}